// round 1
// baseline (speedup 1.0000x reference)
#include <cuda_runtime.h>
#include <cuda_bf16.h>

#define CI 16
#define CO 16
#define DEG 16
#define PTS_PER_BLOCK 16
#define THREADS_PER_BLOCK (PTS_PER_BLOCK * CO)  // 256

// out[p, o] = sum_j sum_d radii[p*DEG+j, d] * sum_i W[d, o, i] * features[nbr(p,j), i]
// Factored: g_d[i] = sum_j r_jd * f[nbr_j, i];  out[o] = sum_{d,i} W[d,o,i] * g_d[i]
// 16 threads per point: lane-in-group = input channel i during gather, output channel o
// during contraction. Neighbor edges for point p are contiguous -> no atomics.
__global__ __launch_bounds__(THREADS_PER_BLOCK)
void PeriodicConvolutionPrep_kernel(
    const float* __restrict__ features,   // [P, CI]
    const float* __restrict__ radii,      // [P*DEG, 3]
    const float* __restrict__ W,          // [3, CO, CI]
    const int*   __restrict__ bs,         // [P, 1+DEG]
    float*       __restrict__ out,        // [P, CO]
    int P)
{
    __shared__ float s_radii[PTS_PER_BLOCK * DEG * 3];      // 768 floats
    __shared__ int   s_bs[PTS_PER_BLOCK * (1 + DEG)];       // 272 ints
    __shared__ float s_g[PTS_PER_BLOCK][3 * CI];            // 768 floats

    const int tid = threadIdx.x;
    const int p0  = blockIdx.x * PTS_PER_BLOCK;
    const int npts = min(PTS_PER_BLOCK, P - p0);

    // ---- Stage per-block radii (contiguous) and bs_slice rows into smem ----
    {
        const float* rbase = radii + (size_t)p0 * (DEG * 3);
        const int nrad = npts * DEG * 3;
        for (int k = tid; k < nrad; k += THREADS_PER_BLOCK) s_radii[k] = rbase[k];
        const int* bbase = bs + (size_t)p0 * (1 + DEG);
        const int nbs = npts * (1 + DEG);
        for (int k = tid; k < nbs; k += THREADS_PER_BLOCK) s_bs[k] = bbase[k];
    }

    const int i  = tid & (CO - 1);   // lane within 16-group: in-channel, then out-channel
    const int gg = tid >> 4;         // point-group within block

    // ---- Preload this thread's W slice W[d][o=i][0..15] into registers ----
    float wreg[3][CI];
#pragma unroll
    for (int d = 0; d < 3; d++) {
        const float4* wrow = (const float4*)(W + (size_t)d * CO * CI + (size_t)i * CI);
#pragma unroll
        for (int q = 0; q < CI / 4; q++) {
            float4 v = __ldg(wrow + q);
            wreg[d][q * 4 + 0] = v.x;
            wreg[d][q * 4 + 1] = v.y;
            wreg[d][q * 4 + 2] = v.z;
            wreg[d][q * 4 + 3] = v.w;
        }
    }

    __syncthreads();

    // ---- Phase 1: gather + radial accumulation. g_d[i] over 16 neighbors ----
    if (gg < npts) {
        float g0 = 0.f, g1 = 0.f, g2 = 0.f;
        const int*   myb = s_bs    + gg * (1 + DEG) + 1;
        const float* myr = s_radii + gg * (DEG * 3);
#pragma unroll
        for (int j = 0; j < DEG; j++) {
            const int   idx = myb[j];                            // LDS broadcast
            const float f   = __ldg(features + (size_t)idx * CI + i);  // 64B/row coalesced
            const float r0  = myr[j * 3 + 0];
            const float r1  = myr[j * 3 + 1];
            const float r2  = myr[j * 3 + 2];
            g0 = fmaf(r0, f, g0);
            g1 = fmaf(r1, f, g1);
            g2 = fmaf(r2, f, g2);
        }
        s_g[gg][0 * CI + i] = g0;
        s_g[gg][1 * CI + i] = g1;
        s_g[gg][2 * CI + i] = g2;
    }
    __syncwarp();   // g produced & consumed within the same warp's 16-groups

    // ---- Phase 2: contraction out[o=i] = sum_{d,ii} W[d,i,ii] * g_d[ii] ----
    if (gg < npts) {
        float acc = 0.f;
#pragma unroll
        for (int d = 0; d < 3; d++) {
#pragma unroll
            for (int ii = 0; ii < CI; ii++)
                acc = fmaf(wreg[d][ii], s_g[gg][d * CI + ii], acc);
        }
        out[(size_t)(p0 + gg) * CO + i] = acc;
    }
}

extern "C" void kernel_launch(void* const* d_in, const int* in_sizes, int n_in,
                              void* d_out, int out_size) {
    const float* features = (const float*)d_in[0];
    const float* radii    = (const float*)d_in[1];
    const float* W        = (const float*)d_in[2];
    const int*   bs       = (const int*)d_in[3];
    float*       out      = (float*)d_out;

    const int P = in_sizes[0] / CI;
    const int blocks = (P + PTS_PER_BLOCK - 1) / PTS_PER_BLOCK;
    PeriodicConvolutionPrep_kernel<<<blocks, THREADS_PER_BLOCK>>>(
        features, radii, W, bs, out, P);
}

// round 2
// speedup vs baseline: 1.2393x; 1.2393x over previous
#include <cuda_runtime.h>
#include <cuda_bf16.h>

#define CI 16
#define CO 16
#define DEG 16
#define BSROW (1 + DEG)               // 17 ints per bs_slice row
#define PTS_PER_BLOCK 16
#define THREADS_PER_BLOCK (PTS_PER_BLOCK * CO)  // 256

// out[p,o] = sum_j sum_d radii[p*DEG+j,d] * sum_i W[d,o,i] * features[nbr(p,j),i]
// Factored: g_d[i] = sum_j r_jd * f[nbr_j,i];  out[o] = sum_{d,i} W[d,o,i] * g_d[i]
//
// Phase 1: 16 lanes per point = (q, c4) grid; lane loads float4 (channels 4*c4..+3)
//          of 4 neighbor rows (j = 4q..4q+3) -> 4 independent LDG.128, max MLP.
//          Partial g reduced over q with shfl_xor(4), shfl_xor(8).
// Phase 2: lane = output channel o; W[d][o][:] in 48 registers; g via smem broadcast.
__global__ __launch_bounds__(THREADS_PER_BLOCK)
void PeriodicConvolutionPrep_kernel(
    const float* __restrict__ features,   // [P, CI]
    const float* __restrict__ radii,      // [P*DEG, 3]
    const float* __restrict__ W,          // [3, CO, CI]
    const int*   __restrict__ bs,         // [P, 1+DEG]
    float*       __restrict__ out,        // [P, CO]
    int P)
{
    __shared__ float s_g[PTS_PER_BLOCK][3 * CI];   // 3 KB

    const int tid = threadIdx.x;
    const int pt  = tid >> 4;            // point within block (0..15)
    const int t16 = tid & 15;            // lane within point group
    const int q   = t16 >> 2;            // neighbor quad (0..3)
    const int c4  = t16 & 3;             // channel quad (0..3)

    int p = blockIdx.x * PTS_PER_BLOCK + pt;
    const bool valid = (p < P);
    if (p >= P) p = P - 1;               // clamp: keep all lanes active for shfl

    // ---- neighbor indices for this thread's quad: bs[p][1+4q .. 1+4q+3] ----
    const int* bp = bs + (size_t)p * BSROW + 1 + 4 * q;
    int idx0 = __ldg(bp + 0);
    int idx1 = __ldg(bp + 1);
    int idx2 = __ldg(bp + 2);
    int idx3 = __ldg(bp + 3);

    // ---- radii for this quad: 12 contiguous floats, 16B-aligned ----
    const float4* rp = (const float4*)(radii + ((size_t)p * DEG + 4 * q) * 3);
    float4 rv0 = __ldg(rp + 0);          // j0:{x,y,z} j1:{w}
    float4 rv1 = __ldg(rp + 1);          // j1:{y,z}   j2:{x,y}  (flattened)
    float4 rv2 = __ldg(rp + 2);
    float r[12] = { rv0.x, rv0.y, rv0.z, rv0.w, rv1.x, rv1.y,
                    rv1.z, rv1.w, rv2.x, rv2.y, rv2.z, rv2.w };

    // ---- 4 independent 16B gathers of feature rows ----
    const float4* fbase = (const float4*)(features) ;
    float4 f0 = __ldg(fbase + (size_t)idx0 * (CI / 4) + c4);
    float4 f1 = __ldg(fbase + (size_t)idx1 * (CI / 4) + c4);
    float4 f2 = __ldg(fbase + (size_t)idx2 * (CI / 4) + c4);
    float4 f3 = __ldg(fbase + (size_t)idx3 * (CI / 4) + c4);

    // ---- partial g[d][ch] over this thread's 4 neighbors: 48 FMA ----
    float g[12];                          // [d*4 + ch]
#pragma unroll
    for (int d = 0; d < 3; d++) {
        g[d * 4 + 0] = r[0 * 3 + d] * f0.x;
        g[d * 4 + 1] = r[0 * 3 + d] * f0.y;
        g[d * 4 + 2] = r[0 * 3 + d] * f0.z;
        g[d * 4 + 3] = r[0 * 3 + d] * f0.w;
        g[d * 4 + 0] = fmaf(r[1 * 3 + d], f1.x, g[d * 4 + 0]);
        g[d * 4 + 1] = fmaf(r[1 * 3 + d], f1.y, g[d * 4 + 1]);
        g[d * 4 + 2] = fmaf(r[1 * 3 + d], f1.z, g[d * 4 + 2]);
        g[d * 4 + 3] = fmaf(r[1 * 3 + d], f1.w, g[d * 4 + 3]);
        g[d * 4 + 0] = fmaf(r[2 * 3 + d], f2.x, g[d * 4 + 0]);
        g[d * 4 + 1] = fmaf(r[2 * 3 + d], f2.y, g[d * 4 + 1]);
        g[d * 4 + 2] = fmaf(r[2 * 3 + d], f2.z, g[d * 4 + 2]);
        g[d * 4 + 3] = fmaf(r[2 * 3 + d], f2.w, g[d * 4 + 3]);
        g[d * 4 + 0] = fmaf(r[3 * 3 + d], f3.x, g[d * 4 + 0]);
        g[d * 4 + 1] = fmaf(r[3 * 3 + d], f3.y, g[d * 4 + 1]);
        g[d * 4 + 2] = fmaf(r[3 * 3 + d], f3.z, g[d * 4 + 2]);
        g[d * 4 + 3] = fmaf(r[3 * 3 + d], f3.w, g[d * 4 + 3]);
    }

    // ---- reduce over q (lanes xor 4, xor 8 stay inside the 16-lane group) ----
#pragma unroll
    for (int v = 0; v < 12; v++) g[v] += __shfl_xor_sync(0xffffffffu, g[v], 4);
#pragma unroll
    for (int v = 0; v < 12; v++) g[v] += __shfl_xor_sync(0xffffffffu, g[v], 8);

    // ---- thread (q=d, c4) publishes g_d[4*c4..+3]; 1 STS.128 for q<3 ----
    if (q < 3) {
        float4 gv = make_float4(g[q * 4 + 0], g[q * 4 + 1], g[q * 4 + 2], g[q * 4 + 3]);
        *(float4*)&s_g[pt][q * CI + 4 * c4] = gv;
    }
    __syncwarp();    // producer & consumers share the warp (2 points / warp)

    // ---- Phase 2: o = t16; W[d][o][:] in registers, g broadcast from smem ----
    float wreg[3][CI];
#pragma unroll
    for (int d = 0; d < 3; d++) {
        const float4* wrow = (const float4*)(W + (size_t)d * CO * CI + (size_t)t16 * CI);
#pragma unroll
        for (int qq = 0; qq < CI / 4; qq++) {
            float4 v = __ldg(wrow + qq);
            wreg[d][qq * 4 + 0] = v.x;
            wreg[d][qq * 4 + 1] = v.y;
            wreg[d][qq * 4 + 2] = v.z;
            wreg[d][qq * 4 + 3] = v.w;
        }
    }

    float acc = 0.f;
#pragma unroll
    for (int d = 0; d < 3; d++) {
#pragma unroll
        for (int ii = 0; ii < CI; ii++)
            acc = fmaf(wreg[d][ii], s_g[pt][d * CI + ii], acc);
    }

    if (valid)
        out[(size_t)p * CO + t16] = acc;
}

extern "C" void kernel_launch(void* const* d_in, const int* in_sizes, int n_in,
                              void* d_out, int out_size) {
    const float* features = (const float*)d_in[0];
    const float* radii    = (const float*)d_in[1];
    const float* W        = (const float*)d_in[2];
    const int*   bs       = (const int*)d_in[3];
    float*       out      = (float*)d_out;

    const int P = in_sizes[0] / CI;
    const int blocks = (P + PTS_PER_BLOCK - 1) / PTS_PER_BLOCK;
    PeriodicConvolutionPrep_kernel<<<blocks, THREADS_PER_BLOCK>>>(
        features, radii, W, bs, out, P);
}

// round 3
// speedup vs baseline: 1.4858x; 1.1989x over previous
#include <cuda_runtime.h>
#include <cuda_bf16.h>

#define CI 16
#define CO 16
#define DEG 16
#define BSROW (1 + DEG)            // 17 ints per bs_slice row
#define GROW 48                    // g row: 3*CI floats

#define MAXP 65536
__device__ float g_buf[(size_t)MAXP * GROW];   // scratch: g[p][d*16+i]

// ---------------------------------------------------------------------------
// Kernel A: gather + radial accumulation.  g[p][d*16+i] = sum_j r[p,j,d]*f[nbr_j,i]
// 16 lanes per point: lane=(q,c4); lane loads float4 (ch 4c4..+3) of neighbors
// 4q..4q+3 -> 4 independent LDG.128. Reduce over q by shfl_xor(4), shfl_xor(8).
// Loop over NITER_A points per group; iterations independent (no barriers).
// ---------------------------------------------------------------------------
#define NITER_A 4
#define PTS_A (16 * NITER_A)       // 64 points per block

__global__ __launch_bounds__(256)
void gather_g_kernel(const float* __restrict__ features,  // [P, CI]
                     const float* __restrict__ radii,     // [P*DEG, 3]
                     const int*   __restrict__ bs,        // [P, 1+DEG]
                     int P)
{
    const int tid  = threadIdx.x;
    const int pt   = tid >> 4;           // group in block (0..15)
    const int t16  = tid & 15;
    const int q    = t16 >> 2;           // neighbor quad
    const int c4   = t16 & 3;            // channel quad
    const int lane = tid & 31;
    const int gbase = lane & ~15;        // group base lane within warp

    const int base = blockIdx.x * PTS_A;

#pragma unroll
    for (int it = 0; it < NITER_A; it++) {
        int p = base + it * 16 + pt;
        const bool valid = (p < P);
        if (p >= P) p = P - 1;           // clamp: keep lanes active for shfl

        // -- indices: 1 coalesced LDG.32 per lane, distribute via 4 shfl --
        const int myv = __ldg(bs + (size_t)p * BSROW + 1 + t16);
        const int idx0 = __shfl_sync(0xffffffffu, myv, gbase + 4 * q + 0);
        const int idx1 = __shfl_sync(0xffffffffu, myv, gbase + 4 * q + 1);
        const int idx2 = __shfl_sync(0xffffffffu, myv, gbase + 4 * q + 2);
        const int idx3 = __shfl_sync(0xffffffffu, myv, gbase + 4 * q + 3);

        // -- radii for this quad: 12 contiguous floats --
        const float4* rp = (const float4*)(radii + ((size_t)p * DEG + 4 * q) * 3);
        float4 rv0 = __ldg(rp + 0);
        float4 rv1 = __ldg(rp + 1);
        float4 rv2 = __ldg(rp + 2);
        float r[12] = { rv0.x, rv0.y, rv0.z, rv0.w, rv1.x, rv1.y,
                        rv1.z, rv1.w, rv2.x, rv2.y, rv2.z, rv2.w };

        // -- 4 independent 16B row gathers --
        const float4* fb = (const float4*)features;
        float4 f0 = __ldg(fb + (size_t)idx0 * (CI / 4) + c4);
        float4 f1 = __ldg(fb + (size_t)idx1 * (CI / 4) + c4);
        float4 f2 = __ldg(fb + (size_t)idx2 * (CI / 4) + c4);
        float4 f3 = __ldg(fb + (size_t)idx3 * (CI / 4) + c4);

        // -- partial g[d][ch]: 48 FMA --
        float g[12];
#pragma unroll
        for (int d = 0; d < 3; d++) {
            g[d * 4 + 0] = r[0 * 3 + d] * f0.x;
            g[d * 4 + 1] = r[0 * 3 + d] * f0.y;
            g[d * 4 + 2] = r[0 * 3 + d] * f0.z;
            g[d * 4 + 3] = r[0 * 3 + d] * f0.w;
            g[d * 4 + 0] = fmaf(r[1 * 3 + d], f1.x, g[d * 4 + 0]);
            g[d * 4 + 1] = fmaf(r[1 * 3 + d], f1.y, g[d * 4 + 1]);
            g[d * 4 + 2] = fmaf(r[1 * 3 + d], f1.z, g[d * 4 + 2]);
            g[d * 4 + 3] = fmaf(r[1 * 3 + d], f1.w, g[d * 4 + 3]);
            g[d * 4 + 0] = fmaf(r[2 * 3 + d], f2.x, g[d * 4 + 0]);
            g[d * 4 + 1] = fmaf(r[2 * 3 + d], f2.y, g[d * 4 + 1]);
            g[d * 4 + 2] = fmaf(r[2 * 3 + d], f2.z, g[d * 4 + 2]);
            g[d * 4 + 3] = fmaf(r[2 * 3 + d], f2.w, g[d * 4 + 3]);
            g[d * 4 + 0] = fmaf(r[3 * 3 + d], f3.x, g[d * 4 + 0]);
            g[d * 4 + 1] = fmaf(r[3 * 3 + d], f3.y, g[d * 4 + 1]);
            g[d * 4 + 2] = fmaf(r[3 * 3 + d], f3.z, g[d * 4 + 2]);
            g[d * 4 + 3] = fmaf(r[3 * 3 + d], f3.w, g[d * 4 + 3]);
        }

        // -- reduce over q --
#pragma unroll
        for (int v = 0; v < 12; v++) g[v] += __shfl_xor_sync(0xffffffffu, g[v], 4);
#pragma unroll
        for (int v = 0; v < 12; v++) g[v] += __shfl_xor_sync(0xffffffffu, g[v], 8);

        // -- lane (q=d, c4) writes g_d[4c4..+3]: STG.128 --
        if (q < 3 && valid) {
            float4 gv = make_float4(g[q * 4 + 0], g[q * 4 + 1],
                                    g[q * 4 + 2], g[q * 4 + 3]);
            *(float4*)(g_buf + (size_t)p * GROW + q * CI + 4 * c4) = gv;
        }
    }
}

// ---------------------------------------------------------------------------
// Kernel B: out[p][o] = sum_k g[p][k] * W[d(k)][o][i(k)],  k = d*16+i.
// Lane = output channel o; W row (48 floats) in registers, amortized over
// NITER_B points. g rows read as 12 broadcast LDG.128 (L2-resident).
// ---------------------------------------------------------------------------
#define NITER_B 10
#define PTS_B (16 * NITER_B)       // 160 points per block

__global__ __launch_bounds__(256)
void contract_w_kernel(const float* __restrict__ W,    // [3, CO, CI]
                       float*       __restrict__ out,  // [P, CO]
                       int P)
{
    const int tid = threadIdx.x;
    const int pt  = tid >> 4;
    const int o   = tid & 15;

    // W[d][o][0..15] for all d: 48 registers
    float wreg[GROW];
#pragma unroll
    for (int d = 0; d < 3; d++) {
        const float4* wrow = (const float4*)(W + (size_t)d * CO * CI + (size_t)o * CI);
#pragma unroll
        for (int qq = 0; qq < 4; qq++) {
            float4 v = __ldg(wrow + qq);
            wreg[d * 16 + qq * 4 + 0] = v.x;
            wreg[d * 16 + qq * 4 + 1] = v.y;
            wreg[d * 16 + qq * 4 + 2] = v.z;
            wreg[d * 16 + qq * 4 + 3] = v.w;
        }
    }

    const int base = blockIdx.x * PTS_B;
#pragma unroll 2
    for (int it = 0; it < NITER_B; it++) {
        const int p = base + it * 16 + pt;
        if (p >= P) break;

        const float4* gp = (const float4*)(g_buf + (size_t)p * GROW);
        float acc = 0.f;
#pragma unroll
        for (int k = 0; k < 12; k++) {
            float4 v = __ldg(gp + k);
            acc = fmaf(wreg[k * 4 + 0], v.x, acc);
            acc = fmaf(wreg[k * 4 + 1], v.y, acc);
            acc = fmaf(wreg[k * 4 + 2], v.z, acc);
            acc = fmaf(wreg[k * 4 + 3], v.w, acc);
        }
        out[(size_t)p * CO + o] = acc;
    }
}

extern "C" void kernel_launch(void* const* d_in, const int* in_sizes, int n_in,
                              void* d_out, int out_size) {
    const float* features = (const float*)d_in[0];
    const float* radii    = (const float*)d_in[1];
    const float* W        = (const float*)d_in[2];
    const int*   bs       = (const int*)d_in[3];
    float*       out      = (float*)d_out;

    const int P = in_sizes[0] / CI;

    const int blocksA = (P + PTS_A - 1) / PTS_A;   // 625 for P=40000
    gather_g_kernel<<<blocksA, 256>>>(features, radii, bs, P);

    const int blocksB = (P + PTS_B - 1) / PTS_B;   // 250 for P=40000
    contract_w_kernel<<<blocksB, 256>>>(W, out, P);
}